// round 14
// baseline (speedup 1.0000x reference)
#include <cuda_runtime.h>
#include <cstdint>
#include <cmath>
#include <cstring>

// ---------------------------------------------------------------------------
// QuantumLayer. Host computes per-row noise power C[row] (input-independent,
// key 42) -> kernel param. k_prep (1 block, __sincosf): amp product + per-row
// rinv and pre-scaled d=0/1 outputs. k_main: 4-chain threefry quad, 16 elems
// per thread, float4 stores. Single pass, no barriers, at the ALU roofline.
// ---------------------------------------------------------------------------

struct RowConst { float c[256]; };   // sum |noise|^2 for d in [2, 8192) per row

__device__ float  g_rinv[256];
__device__ float2 g_fix[256];        // final output values at d=0,1 per row

// ----------------------------- complex helpers -----------------------------
__device__ __forceinline__ float2 cmul(float2 a, float2 b) {
    return make_float2(a.x * b.x - a.y * b.y, a.x * b.y + a.y * b.x);
}
__device__ __forceinline__ float2 cadd(float2 a, float2 b) {
    return make_float2(a.x + b.x, a.y + b.y);
}

struct C2x2 { float2 m00, m01, m10, m11; };

__device__ __forceinline__ C2x2 mmul(const C2x2& A, const C2x2& B) {  // A*B
    C2x2 R;
    R.m00 = cadd(cmul(A.m00, B.m00), cmul(A.m01, B.m10));
    R.m01 = cadd(cmul(A.m00, B.m01), cmul(A.m01, B.m11));
    R.m10 = cadd(cmul(A.m10, B.m00), cmul(A.m11, B.m10));
    R.m11 = cadd(cmul(A.m10, B.m01), cmul(A.m11, B.m11));
    return R;
}

__device__ __forceinline__ float2 shf2(float2 v, int off) {
    return make_float2(__shfl_down_sync(0xFFFFFFFFu, v.x, off),
                       __shfl_down_sync(0xFFFFFFFFu, v.y, off));
}
__device__ __forceinline__ C2x2 shfm(const C2x2& P, int off) {
    C2x2 Q;
    Q.m00 = shf2(P.m00, off); Q.m01 = shf2(P.m01, off);
    Q.m10 = shf2(P.m10, off); Q.m11 = shf2(P.m11, off);
    return Q;
}

// ----------------------------- threefry-2x32 -------------------------------
// 4 chains: counters (ja, jb) under key p (re) and key q (im), interleaved.
struct TF4 { uint32_t ra, rb, ia, ib; };

__device__ __forceinline__ TF4 threefry_quad(
    uint32_t p0, uint32_t p1, uint32_t q0, uint32_t q1,
    uint32_t ja, uint32_t jb) {
    const uint32_t ps2 = 0x1BD11BDAu ^ p0 ^ p1;
    const uint32_t qs2 = 0x1BD11BDAu ^ q0 ^ q1;
    uint32_t a0 = p0, a1 = ja + p1;
    uint32_t b0 = p0, b1 = jb + p1;
    uint32_t c0 = q0, c1 = ja + q1;
    uint32_t d0 = q0, d1 = jb + q1;
#define TF4R(r) { a0 += a1; b0 += b1; c0 += c1; d0 += d1;                       \
                  a1 = __funnelshift_l(a1, a1, (r));                            \
                  b1 = __funnelshift_l(b1, b1, (r));                            \
                  c1 = __funnelshift_l(c1, c1, (r));                            \
                  d1 = __funnelshift_l(d1, d1, (r));                            \
                  a1 ^= a0; b1 ^= b0; c1 ^= c0; d1 ^= d0; }
#define TF4I(pa, pb, qa, qb, i) { a0 += (pa); a1 += (pb) + (i);                 \
                                  b0 += (pa); b1 += (pb) + (i);                 \
                                  c0 += (qa); c1 += (qb) + (i);                 \
                                  d0 += (qa); d1 += (qb) + (i); }
    TF4R(13) TF4R(15) TF4R(26) TF4R(6)
    TF4I(p1, ps2, q1, qs2, 1u)
    TF4R(17) TF4R(29) TF4R(16) TF4R(24)
    TF4I(ps2, p0, qs2, q0, 2u)
    TF4R(13) TF4R(15) TF4R(26) TF4R(6)
    TF4I(p0, p1, q0, q1, 3u)
    TF4R(17) TF4R(29) TF4R(16) TF4R(24)
    TF4I(p1, ps2, q1, qs2, 4u)
    TF4R(13) TF4R(15) TF4R(26) TF4R(6)
    TF4I(ps2, p0, qs2, q0, 5u)
#undef TF4R
#undef TF4I
    TF4 r;
    r.ra = a0 ^ a1; r.rb = b0 ^ b1;
    r.ia = c0 ^ c1; r.ib = d0 ^ d1;
    return r;
}

// pair version (k_prep only)
__device__ __forceinline__ uint2 threefry_pair(uint32_t k0, uint32_t k1,
                                               uint32_t ja, uint32_t jb) {
    uint32_t ks2 = 0x1BD11BDAu ^ k0 ^ k1;
    uint32_t a0 = k0, a1 = ja + k1;
    uint32_t b0 = k0, b1 = jb + k1;
#define TF2(r) { a0 += a1; b0 += b1; \
                 a1 = __funnelshift_l(a1, a1, (r)); b1 = __funnelshift_l(b1, b1, (r)); \
                 a1 ^= a0; b1 ^= b0; }
    TF2(13) TF2(15) TF2(26) TF2(6)
    a0 += k1;  b0 += k1;  a1 += ks2 + 1u; b1 += ks2 + 1u;
    TF2(17) TF2(29) TF2(16) TF2(24)
    a0 += ks2; b0 += ks2; a1 += k0 + 2u;  b1 += k0 + 2u;
    TF2(13) TF2(15) TF2(26) TF2(6)
    a0 += k0;  b0 += k0;  a1 += k1 + 3u;  b1 += k1 + 3u;
    TF2(17) TF2(29) TF2(16) TF2(24)
    a0 += k1;  b0 += k1;  a1 += ks2 + 4u; b1 += ks2 + 4u;
    TF2(13) TF2(15) TF2(26) TF2(6)
    a0 += ks2; b0 += ks2; a1 += k0 + 5u;  b1 += k0 + 5u;
#undef TF2
    return make_uint2(a0 ^ a1, b0 ^ b1);
}

// ------ XLA erf_inv (f32), fast log, coefficients pre-scaled by 0.01 -------
// returns 0.01 * erfinv(x)
__device__ __forceinline__ float xla_erfinv_scaled(float x) {
    float w = -__logf(fmaf(x, -x, 1.0f));
    float p;
    if (w < 5.0f) {
        w -= 2.5f;
        p = 2.81022636e-10f;
        p = fmaf(p, w, 3.43273939e-09f);
        p = fmaf(p, w, -3.5233877e-08f);
        p = fmaf(p, w, -4.39150654e-08f);
        p = fmaf(p, w, 2.1858087e-06f);
        p = fmaf(p, w, -1.25372503e-05f);
        p = fmaf(p, w, -4.17768164e-05f);
        p = fmaf(p, w, 2.46640727e-03f);
        p = fmaf(p, w, 1.50140941e-02f);
    } else {
        w = sqrtf(w) - 3.0f;
        p = -2.00214257e-06f;
        p = fmaf(p, w, 1.00950558e-06f);
        p = fmaf(p, w, 1.34934322e-05f);
        p = fmaf(p, w, -3.67342844e-05f);
        p = fmaf(p, w, 5.73950773e-05f);
        p = fmaf(p, w, -7.6224613e-05f);
        p = fmaf(p, w, 9.43887047e-05f);
        p = fmaf(p, w, 1.00167406e-02f);
        p = fmaf(p, w, 2.83297682e-02f);
    }
    return p * x;
}

__device__ __forceinline__ float bits_to_noise(uint32_t bits) {
    const float LO = -0.99999994039535522461f;   // nextafter(-1, 0)
    float f = __uint_as_float((bits >> 9) | 0x3f800000u) - 1.0f;  // [0,1) exact
    float u = fmaxf(LO, fmaf(f, 2.0f, LO));
    return xla_erfinv_scaled(u);
}

// cheap sqrt: x * rsqrt(x), guarded against x == 0 (rel err ~2^-22)
__device__ __forceinline__ float fast_sqrt(float x) {
    return x * rsqrtf(fmaxf(x, 1e-35f));
}

// ---------------------------------------------------------------------------
// k_prep: 1 block x 256 threads. Warp 0: 78-gate amp product (__sincosf).
// Then thread t = row t: rinv[t] and pre-scaled d=0,1 output pair.
// ---------------------------------------------------------------------------
__global__ void k_prep(
    const float* __restrict__ rx, const float* __restrict__ ry,
    const float* __restrict__ rz,
    uint32_t kre0, uint32_t kre1, uint32_t kim0, uint32_t kim1,
    const __grid_constant__ RowConst C) {

    const int t = threadIdx.x;
    __shared__ float2 sh_amp0, sh_amp1;

    if (t < 32) {
        const int lane = t;
        const int lo = (lane * 78) >> 5;
        const int hi = ((lane + 1) * 78) >> 5;
        C2x2 P;
        P.m00 = {1.f, 0.f}; P.m01 = {0.f, 0.f};
        P.m10 = {0.f, 0.f}; P.m11 = {1.f, 0.f};
        for (int g = lo; g < hi; ++g) {
            float a; int axis;
            if (g < 26)      { a = __ldg(rx + g);      axis = 0; }
            else if (g < 52) { a = __ldg(ry + g - 26); axis = 1; }
            else             { a = __ldg(rz + g - 52); axis = 2; }
            float s, c;
            __sincosf(0.5f * a, &s, &c);
            float2 e00, e01, e10, e11;
            if (axis == 0) {        // rx
                e00 = {c, 0.f}; e01 = {0.f, -s}; e10 = {0.f, -s}; e11 = {c, 0.f};
            } else if (axis == 1) { // ry
                e00 = {c, 0.f}; e01 = {-s, 0.f}; e10 = {s, 0.f};  e11 = {c, 0.f};
            } else {                // rz
                e00 = {c, -s};  e01 = {0.f, 0.f}; e10 = {0.f, 0.f}; e11 = {c, s};
            }
            // fold the reference's in-place aliasing bug
            C2x2 E;
            E.m00 = e00;
            E.m01 = e01;
            E.m10 = cmul(e10, e00);
            E.m11 = cadd(cmul(e10, e01), e11);
            P = mmul(E, P);
        }
        #pragma unroll
        for (int off = 1; off < 32; off <<= 1) {
            C2x2 Q = shfm(P, off);
            if ((lane & (2 * off - 1)) == 0) P = mmul(Q, P);
        }
        if (lane == 0) {
            sh_amp0 = P.m00;   // amplitude at d=0
            sh_amp1 = P.m10;   // amplitude at d=1
        }
    }
    __syncthreads();

    // each thread = one row
    const float2 amp0 = sh_amp0, amp1 = sh_amp1;
    const uint32_t j0 = (uint32_t)(t * 8192);
    uint2 br = threefry_pair(kre0, kre1, j0, j0 + 1);
    uint2 bi = threefry_pair(kim0, kim1, j0, j0 + 1);
    float r0 = bits_to_noise(br.x) + amp0.x;
    float i0 = bits_to_noise(bi.x) + amp0.y;
    float r1 = bits_to_noise(br.y) + amp1.x;
    float i1 = bits_to_noise(bi.y) + amp1.y;
    float fa = fmaf(r0, r0, i0 * i0);
    float fb = fmaf(r1, r1, i1 * i1);
    float rinv = rsqrtf(C.c[t] + fa + fb);
    g_rinv[t] = rinv;
    g_fix[t]  = make_float2(fast_sqrt(fa) * rinv, fast_sqrt(fb) * rinv);
}

// ---------------------------------------------------------------------------
// k_main: grid = 1024 (256 rows x 4 segs), block = 128, 16 elems/thread.
// Thread t: 4 groups of 4 adjacent elements (4t..4t+3) at stride 512;
// two threefry_quads per group -> one float4 store.
// ---------------------------------------------------------------------------
__global__ void k_main(
    float* __restrict__ out,
    uint32_t kre0, uint32_t kre1, uint32_t kim0, uint32_t kim1) {

    const int t   = threadIdx.x;
    const int bid = blockIdx.x;
    const int row = bid >> 2;
    const int seg = bid & 3;

    const float rinv = g_rinv[row];   // broadcast load; k_prep wrote this

    const uint32_t base = (uint32_t)(row * 8192 + seg * 2048 + t * 4);
    float4* o4 = reinterpret_cast<float4*>(out) + (base >> 2);

#pragma unroll
    for (int k = 0; k < 4; k++) {
        const uint32_t j = base + k * 512;
        TF4 bA = threefry_quad(kre0, kre1, kim0, kim1, j, j + 1);
        TF4 bB = threefry_quad(kre0, kre1, kim0, kim1, j + 2, j + 3);
        float re0 = bits_to_noise(bA.ra), re1 = bits_to_noise(bA.rb);
        float im0 = bits_to_noise(bA.ia), im1 = bits_to_noise(bA.ib);
        float re2 = bits_to_noise(bB.ra), re3 = bits_to_noise(bB.rb);
        float im2 = bits_to_noise(bB.ia), im3 = bits_to_noise(bB.ib);
        float4 v;
        v.x = fast_sqrt(fmaf(re0, re0, im0 * im0)) * rinv;
        v.y = fast_sqrt(fmaf(re1, re1, im1 * im1)) * rinv;
        v.z = fast_sqrt(fmaf(re2, re2, im2 * im2)) * rinv;
        v.w = fast_sqrt(fmaf(re3, re3, im3 * im3)) * rinv;
        o4[k * 128] = v;
    }

    // d = 0,1 fixup: overwrite with the pre-scaled values from k_prep
    if (seg == 0 && t == 0) {
        reinterpret_cast<float2*>(out)[row * 4096] = g_fix[row];
    }
}

// =========================== host-side replicas ============================
static inline uint32_t h_rotl(uint32_t x, int r) { return (x << r) | (x >> (32 - r)); }
static void h_threefry(uint32_t k0, uint32_t k1, uint32_t x0, uint32_t x1,
                       uint32_t* o0, uint32_t* o1) {
    uint32_t ks2 = 0x1BD11BDAu ^ k0 ^ k1;
#define HTF(r) { x0 += x1; x1 = h_rotl(x1, (r)); x1 ^= x0; }
    x0 += k0;  x1 += k1;
    HTF(13) HTF(15) HTF(26) HTF(6)
    x0 += k1;  x1 += ks2 + 1u;
    HTF(17) HTF(29) HTF(16) HTF(24)
    x0 += ks2; x1 += k0 + 2u;
    HTF(13) HTF(15) HTF(26) HTF(6)
    x0 += k0;  x1 += k1 + 3u;
    HTF(17) HTF(29) HTF(16) HTF(24)
    x0 += k1;  x1 += ks2 + 4u;
    HTF(13) HTF(15) HTF(26) HTF(6)
    x0 += ks2; x1 += k0 + 5u;
#undef HTF
    *o0 = x0; *o1 = x1;
}

static float h_erfinv(float x) {
    float w = -log1pf(-x * x);
    float p;
    if (w < 5.0f) {
        w -= 2.5f;
        p = 2.81022636e-08f;
        p = p * w + 3.43273939e-07f;
        p = p * w + -3.5233877e-06f;
        p = p * w + -4.39150654e-06f;
        p = p * w + 0.00021858087f;
        p = p * w + -0.00125372503f;
        p = p * w + -0.00417768164f;
        p = p * w + 0.246640727f;
        p = p * w + 1.50140941f;
    } else {
        w = sqrtf(w) - 3.0f;
        p = -0.000200214257f;
        p = p * w + 0.000100950558f;
        p = p * w + 0.00134934322f;
        p = p * w + -0.00367342844f;
        p = p * w + 0.00573950773f;
        p = p * w + -0.0076224613f;
        p = p * w + 0.00943887047f;
        p = p * w + 1.00167406f;
        p = p * w + 2.83297682f;
    }
    return p * x;
}

static float h_noise(uint32_t k0, uint32_t k1, uint32_t j) {
    const float LO = -0.99999994039535522461f;
    uint32_t o0, o1;
    h_threefry(k0, k1, 0u, j, &o0, &o1);
    uint32_t bits = o0 ^ o1;
    uint32_t fb = (bits >> 9) | 0x3f800000u;
    float F;
    memcpy(&F, &fb, 4);
    float f = F - 1.0f;
    float u = f * 2.0f + LO;
    if (u < LO) u = LO;
    return h_erfinv(u) * 0.01f;
}

// ---------------------------------------------------------------------------
extern "C" void kernel_launch(void* const* d_in, const int* in_sizes, int n_in,
                              void* d_out, int out_size) {
    // metadata order: x (unused), rx_params, ry_params, rz_params
    const float* rx = (const float*)d_in[1];
    const float* ry = (const float*)d_in[2];
    const float* rz = (const float*)d_in[3];
    float* out = (float*)d_out;

    // foldlike split of key(42) = (0, 42)
    uint32_t kre0, kre1, kim0, kim1;
    h_threefry(0u, 42u, 0u, 0u, &kre0, &kre1);
    h_threefry(0u, 42u, 0u, 1u, &kim0, &kim1);

    // per-row noise-power constants (d = 2..8191): input-independent,
    // deterministically recomputed every call on the host.
    RowConst C;
    for (int row = 0; row < 256; row++) {
        double acc = 0.0;
        uint32_t jbase = (uint32_t)(row * 8192);
        for (int d = 2; d < 8192; d++) {
            float re = h_noise(kre0, kre1, jbase + (uint32_t)d);
            float im = h_noise(kim0, kim1, jbase + (uint32_t)d);
            acc += (double)re * re + (double)im * im;
        }
        C.c[row] = (float)acc;
    }

    k_prep<<<1, 256>>>(rx, ry, rz, kre0, kre1, kim0, kim1, C);
    k_main<<<1024, 128>>>(out, kre0, kre1, kim0, kim1);
}

// round 15
// speedup vs baseline: 1.1174x; 1.1174x over previous
#include <cuda_runtime.h>
#include <cstdint>
#include <cmath>
#include <cstring>

// ---------------------------------------------------------------------------
// QuantumLayer. Host computes per-row noise power C[row] (input-independent,
// key 42) -> kernel param. k_prep (1 block, __sincosf): amp product + per-row
// rinv and pre-scaled d=0/1 outputs. k_main: grid 4096 x 128, 4 elems/thread
// (2 interleaved threefry quads = 8 chains), one float4 store per thread.
// Max warp pool for ALU-pipe utilization. Single pass, no barriers.
// ---------------------------------------------------------------------------

struct RowConst { float c[256]; };   // sum |noise|^2 for d in [2, 8192) per row

__device__ float  g_rinv[256];
__device__ float2 g_fix[256];        // final output values at d=0,1 per row

// ----------------------------- complex helpers -----------------------------
__device__ __forceinline__ float2 cmul(float2 a, float2 b) {
    return make_float2(a.x * b.x - a.y * b.y, a.x * b.y + a.y * b.x);
}
__device__ __forceinline__ float2 cadd(float2 a, float2 b) {
    return make_float2(a.x + b.x, a.y + b.y);
}

struct C2x2 { float2 m00, m01, m10, m11; };

__device__ __forceinline__ C2x2 mmul(const C2x2& A, const C2x2& B) {  // A*B
    C2x2 R;
    R.m00 = cadd(cmul(A.m00, B.m00), cmul(A.m01, B.m10));
    R.m01 = cadd(cmul(A.m00, B.m01), cmul(A.m01, B.m11));
    R.m10 = cadd(cmul(A.m10, B.m00), cmul(A.m11, B.m10));
    R.m11 = cadd(cmul(A.m10, B.m01), cmul(A.m11, B.m11));
    return R;
}

__device__ __forceinline__ float2 shf2(float2 v, int off) {
    return make_float2(__shfl_down_sync(0xFFFFFFFFu, v.x, off),
                       __shfl_down_sync(0xFFFFFFFFu, v.y, off));
}
__device__ __forceinline__ C2x2 shfm(const C2x2& P, int off) {
    C2x2 Q;
    Q.m00 = shf2(P.m00, off); Q.m01 = shf2(P.m01, off);
    Q.m10 = shf2(P.m10, off); Q.m11 = shf2(P.m11, off);
    return Q;
}

// ----------------------------- threefry-2x32 -------------------------------
// 4 chains: counters (ja, jb) under key p (re) and key q (im), interleaved.
struct TF4 { uint32_t ra, rb, ia, ib; };

__device__ __forceinline__ TF4 threefry_quad(
    uint32_t p0, uint32_t p1, uint32_t q0, uint32_t q1,
    uint32_t ja, uint32_t jb) {
    const uint32_t ps2 = 0x1BD11BDAu ^ p0 ^ p1;
    const uint32_t qs2 = 0x1BD11BDAu ^ q0 ^ q1;
    uint32_t a0 = p0, a1 = ja + p1;
    uint32_t b0 = p0, b1 = jb + p1;
    uint32_t c0 = q0, c1 = ja + q1;
    uint32_t d0 = q0, d1 = jb + q1;
#define TF4R(r) { a0 += a1; b0 += b1; c0 += c1; d0 += d1;                       \
                  a1 = __funnelshift_l(a1, a1, (r));                            \
                  b1 = __funnelshift_l(b1, b1, (r));                            \
                  c1 = __funnelshift_l(c1, c1, (r));                            \
                  d1 = __funnelshift_l(d1, d1, (r));                            \
                  a1 ^= a0; b1 ^= b0; c1 ^= c0; d1 ^= d0; }
#define TF4I(pa, pb, qa, qb, i) { a0 += (pa); a1 += (pb) + (i);                 \
                                  b0 += (pa); b1 += (pb) + (i);                 \
                                  c0 += (qa); c1 += (qb) + (i);                 \
                                  d0 += (qa); d1 += (qb) + (i); }
    TF4R(13) TF4R(15) TF4R(26) TF4R(6)
    TF4I(p1, ps2, q1, qs2, 1u)
    TF4R(17) TF4R(29) TF4R(16) TF4R(24)
    TF4I(ps2, p0, qs2, q0, 2u)
    TF4R(13) TF4R(15) TF4R(26) TF4R(6)
    TF4I(p0, p1, q0, q1, 3u)
    TF4R(17) TF4R(29) TF4R(16) TF4R(24)
    TF4I(p1, ps2, q1, qs2, 4u)
    TF4R(13) TF4R(15) TF4R(26) TF4R(6)
    TF4I(ps2, p0, qs2, q0, 5u)
#undef TF4R
#undef TF4I
    TF4 r;
    r.ra = a0 ^ a1; r.rb = b0 ^ b1;
    r.ia = c0 ^ c1; r.ib = d0 ^ d1;
    return r;
}

// pair version (k_prep only)
__device__ __forceinline__ uint2 threefry_pair(uint32_t k0, uint32_t k1,
                                               uint32_t ja, uint32_t jb) {
    uint32_t ks2 = 0x1BD11BDAu ^ k0 ^ k1;
    uint32_t a0 = k0, a1 = ja + k1;
    uint32_t b0 = k0, b1 = jb + k1;
#define TF2(r) { a0 += a1; b0 += b1; \
                 a1 = __funnelshift_l(a1, a1, (r)); b1 = __funnelshift_l(b1, b1, (r)); \
                 a1 ^= a0; b1 ^= b0; }
    TF2(13) TF2(15) TF2(26) TF2(6)
    a0 += k1;  b0 += k1;  a1 += ks2 + 1u; b1 += ks2 + 1u;
    TF2(17) TF2(29) TF2(16) TF2(24)
    a0 += ks2; b0 += ks2; a1 += k0 + 2u;  b1 += k0 + 2u;
    TF2(13) TF2(15) TF2(26) TF2(6)
    a0 += k0;  b0 += k0;  a1 += k1 + 3u;  b1 += k1 + 3u;
    TF2(17) TF2(29) TF2(16) TF2(24)
    a0 += k1;  b0 += k1;  a1 += ks2 + 4u; b1 += ks2 + 4u;
    TF2(13) TF2(15) TF2(26) TF2(6)
    a0 += ks2; b0 += ks2; a1 += k0 + 5u;  b1 += k0 + 5u;
#undef TF2
    return make_uint2(a0 ^ a1, b0 ^ b1);
}

// ------ XLA erf_inv (f32), fast log, coefficients pre-scaled by 0.01 -------
// returns 0.01 * erfinv(x)
__device__ __forceinline__ float xla_erfinv_scaled(float x) {
    float w = -__logf(fmaf(x, -x, 1.0f));
    float p;
    if (w < 5.0f) {
        w -= 2.5f;
        p = 2.81022636e-10f;
        p = fmaf(p, w, 3.43273939e-09f);
        p = fmaf(p, w, -3.5233877e-08f);
        p = fmaf(p, w, -4.39150654e-08f);
        p = fmaf(p, w, 2.1858087e-06f);
        p = fmaf(p, w, -1.25372503e-05f);
        p = fmaf(p, w, -4.17768164e-05f);
        p = fmaf(p, w, 2.46640727e-03f);
        p = fmaf(p, w, 1.50140941e-02f);
    } else {
        w = sqrtf(w) - 3.0f;
        p = -2.00214257e-06f;
        p = fmaf(p, w, 1.00950558e-06f);
        p = fmaf(p, w, 1.34934322e-05f);
        p = fmaf(p, w, -3.67342844e-05f);
        p = fmaf(p, w, 5.73950773e-05f);
        p = fmaf(p, w, -7.6224613e-05f);
        p = fmaf(p, w, 9.43887047e-05f);
        p = fmaf(p, w, 1.00167406e-02f);
        p = fmaf(p, w, 2.83297682e-02f);
    }
    return p * x;
}

__device__ __forceinline__ float bits_to_noise(uint32_t bits) {
    const float LO = -0.99999994039535522461f;   // nextafter(-1, 0)
    float f = __uint_as_float((bits >> 9) | 0x3f800000u) - 1.0f;  // [0,1) exact
    float u = fmaxf(LO, fmaf(f, 2.0f, LO));
    return xla_erfinv_scaled(u);
}

// cheap sqrt: x * rsqrt(x), guarded against x == 0 (rel err ~2^-22)
__device__ __forceinline__ float fast_sqrt(float x) {
    return x * rsqrtf(fmaxf(x, 1e-35f));
}

// ---------------------------------------------------------------------------
// k_prep: 1 block x 256 threads. Warp 0: 78-gate amp product (__sincosf).
// Then thread t = row t: rinv[t] and pre-scaled d=0,1 output pair.
// ---------------------------------------------------------------------------
__global__ void k_prep(
    const float* __restrict__ rx, const float* __restrict__ ry,
    const float* __restrict__ rz,
    uint32_t kre0, uint32_t kre1, uint32_t kim0, uint32_t kim1,
    const __grid_constant__ RowConst C) {

    const int t = threadIdx.x;
    __shared__ float2 sh_amp0, sh_amp1;

    if (t < 32) {
        const int lane = t;
        const int lo = (lane * 78) >> 5;
        const int hi = ((lane + 1) * 78) >> 5;
        C2x2 P;
        P.m00 = {1.f, 0.f}; P.m01 = {0.f, 0.f};
        P.m10 = {0.f, 0.f}; P.m11 = {1.f, 0.f};
        for (int g = lo; g < hi; ++g) {
            float a; int axis;
            if (g < 26)      { a = __ldg(rx + g);      axis = 0; }
            else if (g < 52) { a = __ldg(ry + g - 26); axis = 1; }
            else             { a = __ldg(rz + g - 52); axis = 2; }
            float s, c;
            __sincosf(0.5f * a, &s, &c);
            float2 e00, e01, e10, e11;
            if (axis == 0) {        // rx
                e00 = {c, 0.f}; e01 = {0.f, -s}; e10 = {0.f, -s}; e11 = {c, 0.f};
            } else if (axis == 1) { // ry
                e00 = {c, 0.f}; e01 = {-s, 0.f}; e10 = {s, 0.f};  e11 = {c, 0.f};
            } else {                // rz
                e00 = {c, -s};  e01 = {0.f, 0.f}; e10 = {0.f, 0.f}; e11 = {c, s};
            }
            // fold the reference's in-place aliasing bug
            C2x2 E;
            E.m00 = e00;
            E.m01 = e01;
            E.m10 = cmul(e10, e00);
            E.m11 = cadd(cmul(e10, e01), e11);
            P = mmul(E, P);
        }
        #pragma unroll
        for (int off = 1; off < 32; off <<= 1) {
            C2x2 Q = shfm(P, off);
            if ((lane & (2 * off - 1)) == 0) P = mmul(Q, P);
        }
        if (lane == 0) {
            sh_amp0 = P.m00;   // amplitude at d=0
            sh_amp1 = P.m10;   // amplitude at d=1
        }
    }
    __syncthreads();

    // each thread = one row
    const float2 amp0 = sh_amp0, amp1 = sh_amp1;
    const uint32_t j0 = (uint32_t)(t * 8192);
    uint2 br = threefry_pair(kre0, kre1, j0, j0 + 1);
    uint2 bi = threefry_pair(kim0, kim1, j0, j0 + 1);
    float r0 = bits_to_noise(br.x) + amp0.x;
    float i0 = bits_to_noise(bi.x) + amp0.y;
    float r1 = bits_to_noise(br.y) + amp1.x;
    float i1 = bits_to_noise(bi.y) + amp1.y;
    float fa = fmaf(r0, r0, i0 * i0);
    float fb = fmaf(r1, r1, i1 * i1);
    float rinv = rsqrtf(C.c[t] + fa + fb);
    g_rinv[t] = rinv;
    g_fix[t]  = make_float2(fast_sqrt(fa) * rinv, fast_sqrt(fb) * rinv);
}

// ---------------------------------------------------------------------------
// k_main: grid = 4096 (256 rows x 16 segs), block = 128, 4 elems/thread.
// Thread t: elements 4t..4t+3 of its segment, 2 interleaved quads,
// single float4 store. Maximum warp pool for the ALU pipe.
// ---------------------------------------------------------------------------
__global__ void k_main(
    float* __restrict__ out,
    uint32_t kre0, uint32_t kre1, uint32_t kim0, uint32_t kim1) {

    const int t   = threadIdx.x;
    const int bid = blockIdx.x;
    const int row = bid >> 4;
    const int seg = bid & 15;

    const float rinv = g_rinv[row];   // broadcast load; k_prep wrote this

    const uint32_t j = (uint32_t)(row * 8192 + seg * 512 + t * 4);

    TF4 bA = threefry_quad(kre0, kre1, kim0, kim1, j, j + 1);
    TF4 bB = threefry_quad(kre0, kre1, kim0, kim1, j + 2, j + 3);
    float re0 = bits_to_noise(bA.ra), re1 = bits_to_noise(bA.rb);
    float im0 = bits_to_noise(bA.ia), im1 = bits_to_noise(bA.ib);
    float re2 = bits_to_noise(bB.ra), re3 = bits_to_noise(bB.rb);
    float im2 = bits_to_noise(bB.ia), im3 = bits_to_noise(bB.ib);
    float4 v;
    v.x = fast_sqrt(fmaf(re0, re0, im0 * im0)) * rinv;
    v.y = fast_sqrt(fmaf(re1, re1, im1 * im1)) * rinv;
    v.z = fast_sqrt(fmaf(re2, re2, im2 * im2)) * rinv;
    v.w = fast_sqrt(fmaf(re3, re3, im3 * im3)) * rinv;
    reinterpret_cast<float4*>(out)[j >> 2] = v;

    // d = 0,1 fixup: overwrite with the pre-scaled values from k_prep
    if (bid == (row << 4) && t == 0 && seg == 0) {
        reinterpret_cast<float2*>(out)[row * 4096] = g_fix[row];
    }
}

// =========================== host-side replicas ============================
static inline uint32_t h_rotl(uint32_t x, int r) { return (x << r) | (x >> (32 - r)); }
static void h_threefry(uint32_t k0, uint32_t k1, uint32_t x0, uint32_t x1,
                       uint32_t* o0, uint32_t* o1) {
    uint32_t ks2 = 0x1BD11BDAu ^ k0 ^ k1;
#define HTF(r) { x0 += x1; x1 = h_rotl(x1, (r)); x1 ^= x0; }
    x0 += k0;  x1 += k1;
    HTF(13) HTF(15) HTF(26) HTF(6)
    x0 += k1;  x1 += ks2 + 1u;
    HTF(17) HTF(29) HTF(16) HTF(24)
    x0 += ks2; x1 += k0 + 2u;
    HTF(13) HTF(15) HTF(26) HTF(6)
    x0 += k0;  x1 += k1 + 3u;
    HTF(17) HTF(29) HTF(16) HTF(24)
    x0 += k1;  x1 += ks2 + 4u;
    HTF(13) HTF(15) HTF(26) HTF(6)
    x0 += ks2; x1 += k0 + 5u;
#undef HTF
    *o0 = x0; *o1 = x1;
}

static float h_erfinv(float x) {
    float w = -log1pf(-x * x);
    float p;
    if (w < 5.0f) {
        w -= 2.5f;
        p = 2.81022636e-08f;
        p = p * w + 3.43273939e-07f;
        p = p * w + -3.5233877e-06f;
        p = p * w + -4.39150654e-06f;
        p = p * w + 0.00021858087f;
        p = p * w + -0.00125372503f;
        p = p * w + -0.00417768164f;
        p = p * w + 0.246640727f;
        p = p * w + 1.50140941f;
    } else {
        w = sqrtf(w) - 3.0f;
        p = -0.000200214257f;
        p = p * w + 0.000100950558f;
        p = p * w + 0.00134934322f;
        p = p * w + -0.00367342844f;
        p = p * w + 0.00573950773f;
        p = p * w + -0.0076224613f;
        p = p * w + 0.00943887047f;
        p = p * w + 1.00167406f;
        p = p * w + 2.83297682f;
    }
    return p * x;
}

static float h_noise(uint32_t k0, uint32_t k1, uint32_t j) {
    const float LO = -0.99999994039535522461f;
    uint32_t o0, o1;
    h_threefry(k0, k1, 0u, j, &o0, &o1);
    uint32_t bits = o0 ^ o1;
    uint32_t fb = (bits >> 9) | 0x3f800000u;
    float F;
    memcpy(&F, &fb, 4);
    float f = F - 1.0f;
    float u = f * 2.0f + LO;
    if (u < LO) u = LO;
    return h_erfinv(u) * 0.01f;
}

// ---------------------------------------------------------------------------
extern "C" void kernel_launch(void* const* d_in, const int* in_sizes, int n_in,
                              void* d_out, int out_size) {
    // metadata order: x (unused), rx_params, ry_params, rz_params
    const float* rx = (const float*)d_in[1];
    const float* ry = (const float*)d_in[2];
    const float* rz = (const float*)d_in[3];
    float* out = (float*)d_out;

    // foldlike split of key(42) = (0, 42)
    uint32_t kre0, kre1, kim0, kim1;
    h_threefry(0u, 42u, 0u, 0u, &kre0, &kre1);
    h_threefry(0u, 42u, 0u, 1u, &kim0, &kim1);

    // per-row noise-power constants (d = 2..8191): input-independent,
    // deterministically recomputed every call on the host.
    RowConst C;
    for (int row = 0; row < 256; row++) {
        double acc = 0.0;
        uint32_t jbase = (uint32_t)(row * 8192);
        for (int d = 2; d < 8192; d++) {
            float re = h_noise(kre0, kre1, jbase + (uint32_t)d);
            float im = h_noise(kim0, kim1, jbase + (uint32_t)d);
            acc += (double)re * re + (double)im * im;
        }
        C.c[row] = (float)acc;
    }

    k_prep<<<1, 256>>>(rx, ry, rz, kre0, kre1, kim0, kim1, C);
    k_main<<<4096, 128>>>(out, kre0, kre1, kim0, kim1);
}

// round 16
// speedup vs baseline: 1.1263x; 1.0080x over previous
#include <cuda_runtime.h>
#include <cstdint>
#include <cmath>
#include <cstring>

// ---------------------------------------------------------------------------
// QuantumLayer. Host computes per-row noise power C[row] (input-independent,
// key 42) -> kernel param. k_prep: grid 256 x 32 — one warp per row, each warp
// redundantly computes the 78-gate amp product, lane 0 derives rinv + d=0/1
// outputs for its row (parallel, no syncthreads). k_main: grid 8192 x 128,
// 2 elems/thread (one interleaved threefry quad), float2 store.
// ---------------------------------------------------------------------------

struct RowConst { float c[256]; };   // sum |noise|^2 for d in [2, 8192) per row

__device__ float  g_rinv[256];
__device__ float2 g_fix[256];        // final output values at d=0,1 per row

// ----------------------------- complex helpers -----------------------------
__device__ __forceinline__ float2 cmul(float2 a, float2 b) {
    return make_float2(a.x * b.x - a.y * b.y, a.x * b.y + a.y * b.x);
}
__device__ __forceinline__ float2 cadd(float2 a, float2 b) {
    return make_float2(a.x + b.x, a.y + b.y);
}

struct C2x2 { float2 m00, m01, m10, m11; };

__device__ __forceinline__ C2x2 mmul(const C2x2& A, const C2x2& B) {  // A*B
    C2x2 R;
    R.m00 = cadd(cmul(A.m00, B.m00), cmul(A.m01, B.m10));
    R.m01 = cadd(cmul(A.m00, B.m01), cmul(A.m01, B.m11));
    R.m10 = cadd(cmul(A.m10, B.m00), cmul(A.m11, B.m10));
    R.m11 = cadd(cmul(A.m10, B.m01), cmul(A.m11, B.m11));
    return R;
}

__device__ __forceinline__ float2 shf2(float2 v, int off) {
    return make_float2(__shfl_down_sync(0xFFFFFFFFu, v.x, off),
                       __shfl_down_sync(0xFFFFFFFFu, v.y, off));
}
__device__ __forceinline__ C2x2 shfm(const C2x2& P, int off) {
    C2x2 Q;
    Q.m00 = shf2(P.m00, off); Q.m01 = shf2(P.m01, off);
    Q.m10 = shf2(P.m10, off); Q.m11 = shf2(P.m11, off);
    return Q;
}

// ----------------------------- threefry-2x32 -------------------------------
// 4 chains: counters (ja, jb) under key p (re) and key q (im), interleaved.
struct TF4 { uint32_t ra, rb, ia, ib; };

__device__ __forceinline__ TF4 threefry_quad(
    uint32_t p0, uint32_t p1, uint32_t q0, uint32_t q1,
    uint32_t ja, uint32_t jb) {
    const uint32_t ps2 = 0x1BD11BDAu ^ p0 ^ p1;
    const uint32_t qs2 = 0x1BD11BDAu ^ q0 ^ q1;
    uint32_t a0 = p0, a1 = ja + p1;
    uint32_t b0 = p0, b1 = jb + p1;
    uint32_t c0 = q0, c1 = ja + q1;
    uint32_t d0 = q0, d1 = jb + q1;
#define TF4R(r) { a0 += a1; b0 += b1; c0 += c1; d0 += d1;                       \
                  a1 = __funnelshift_l(a1, a1, (r));                            \
                  b1 = __funnelshift_l(b1, b1, (r));                            \
                  c1 = __funnelshift_l(c1, c1, (r));                            \
                  d1 = __funnelshift_l(d1, d1, (r));                            \
                  a1 ^= a0; b1 ^= b0; c1 ^= c0; d1 ^= d0; }
#define TF4I(pa, pb, qa, qb, i) { a0 += (pa); a1 += (pb) + (i);                 \
                                  b0 += (pa); b1 += (pb) + (i);                 \
                                  c0 += (qa); c1 += (qb) + (i);                 \
                                  d0 += (qa); d1 += (qb) + (i); }
    TF4R(13) TF4R(15) TF4R(26) TF4R(6)
    TF4I(p1, ps2, q1, qs2, 1u)
    TF4R(17) TF4R(29) TF4R(16) TF4R(24)
    TF4I(ps2, p0, qs2, q0, 2u)
    TF4R(13) TF4R(15) TF4R(26) TF4R(6)
    TF4I(p0, p1, q0, q1, 3u)
    TF4R(17) TF4R(29) TF4R(16) TF4R(24)
    TF4I(p1, ps2, q1, qs2, 4u)
    TF4R(13) TF4R(15) TF4R(26) TF4R(6)
    TF4I(ps2, p0, qs2, q0, 5u)
#undef TF4R
#undef TF4I
    TF4 r;
    r.ra = a0 ^ a1; r.rb = b0 ^ b1;
    r.ia = c0 ^ c1; r.ib = d0 ^ d1;
    return r;
}

// ------ XLA erf_inv (f32), fast log, coefficients pre-scaled by 0.01 -------
// returns 0.01 * erfinv(x)
__device__ __forceinline__ float xla_erfinv_scaled(float x) {
    float w = -__logf(fmaf(x, -x, 1.0f));
    float p;
    if (w < 5.0f) {
        w -= 2.5f;
        p = 2.81022636e-10f;
        p = fmaf(p, w, 3.43273939e-09f);
        p = fmaf(p, w, -3.5233877e-08f);
        p = fmaf(p, w, -4.39150654e-08f);
        p = fmaf(p, w, 2.1858087e-06f);
        p = fmaf(p, w, -1.25372503e-05f);
        p = fmaf(p, w, -4.17768164e-05f);
        p = fmaf(p, w, 2.46640727e-03f);
        p = fmaf(p, w, 1.50140941e-02f);
    } else {
        w = sqrtf(w) - 3.0f;
        p = -2.00214257e-06f;
        p = fmaf(p, w, 1.00950558e-06f);
        p = fmaf(p, w, 1.34934322e-05f);
        p = fmaf(p, w, -3.67342844e-05f);
        p = fmaf(p, w, 5.73950773e-05f);
        p = fmaf(p, w, -7.6224613e-05f);
        p = fmaf(p, w, 9.43887047e-05f);
        p = fmaf(p, w, 1.00167406e-02f);
        p = fmaf(p, w, 2.83297682e-02f);
    }
    return p * x;
}

__device__ __forceinline__ float bits_to_noise(uint32_t bits) {
    const float LO = -0.99999994039535522461f;   // nextafter(-1, 0)
    float f = __uint_as_float((bits >> 9) | 0x3f800000u) - 1.0f;  // [0,1) exact
    float u = fmaxf(LO, fmaf(f, 2.0f, LO));
    return xla_erfinv_scaled(u);
}

// cheap sqrt: x * rsqrt(x), guarded against x == 0 (rel err ~2^-22)
__device__ __forceinline__ float fast_sqrt(float x) {
    return x * rsqrtf(fmaxf(x, 1e-35f));
}

// ---------------------------------------------------------------------------
// k_prep: grid = 256, block = 32. Each warp redundantly computes the 78-gate
// amp product; lane 0 derives rinv + pre-scaled d=0,1 outputs for row = bid.
// ---------------------------------------------------------------------------
__global__ __launch_bounds__(32) void k_prep(
    const float* __restrict__ rx, const float* __restrict__ ry,
    const float* __restrict__ rz,
    uint32_t kre0, uint32_t kre1, uint32_t kim0, uint32_t kim1,
    const __grid_constant__ RowConst C) {

    const int lane = threadIdx.x;
    const int row  = blockIdx.x;

    const int lo = (lane * 78) >> 5;
    const int hi = ((lane + 1) * 78) >> 5;
    C2x2 P;
    P.m00 = {1.f, 0.f}; P.m01 = {0.f, 0.f};
    P.m10 = {0.f, 0.f}; P.m11 = {1.f, 0.f};
    for (int g = lo; g < hi; ++g) {
        float a; int axis;
        if (g < 26)      { a = __ldg(rx + g);      axis = 0; }
        else if (g < 52) { a = __ldg(ry + g - 26); axis = 1; }
        else             { a = __ldg(rz + g - 52); axis = 2; }
        float s, c;
        __sincosf(0.5f * a, &s, &c);
        float2 e00, e01, e10, e11;
        if (axis == 0) {        // rx
            e00 = {c, 0.f}; e01 = {0.f, -s}; e10 = {0.f, -s}; e11 = {c, 0.f};
        } else if (axis == 1) { // ry
            e00 = {c, 0.f}; e01 = {-s, 0.f}; e10 = {s, 0.f};  e11 = {c, 0.f};
        } else {                // rz
            e00 = {c, -s};  e01 = {0.f, 0.f}; e10 = {0.f, 0.f}; e11 = {c, s};
        }
        // fold the reference's in-place aliasing bug
        C2x2 E;
        E.m00 = e00;
        E.m01 = e01;
        E.m10 = cmul(e10, e00);
        E.m11 = cadd(cmul(e10, e01), e11);
        P = mmul(E, P);
    }
    #pragma unroll
    for (int off = 1; off < 32; off <<= 1) {
        C2x2 Q = shfm(P, off);
        if ((lane & (2 * off - 1)) == 0) P = mmul(Q, P);
    }

    if (lane == 0) {
        const float2 amp0 = P.m00;   // amplitude at d=0
        const float2 amp1 = P.m10;   // amplitude at d=1
        const uint32_t j0 = (uint32_t)(row * 8192);
        TF4 b = threefry_quad(kre0, kre1, kim0, kim1, j0, j0 + 1);
        float r0 = bits_to_noise(b.ra) + amp0.x;
        float i0 = bits_to_noise(b.ia) + amp0.y;
        float r1 = bits_to_noise(b.rb) + amp1.x;
        float i1 = bits_to_noise(b.ib) + amp1.y;
        float fa = fmaf(r0, r0, i0 * i0);
        float fb = fmaf(r1, r1, i1 * i1);
        float rinv = rsqrtf(C.c[row] + fa + fb);
        g_rinv[row] = rinv;
        g_fix[row]  = make_float2(fast_sqrt(fa) * rinv, fast_sqrt(fb) * rinv);
    }
}

// ---------------------------------------------------------------------------
// k_main: grid = 8192 (256 rows x 32 segs), block = 128, 2 elems/thread.
// Thread t: elements (2t, 2t+1) of its 256-element segment, one interleaved
// threefry quad, single float2 store.
// ---------------------------------------------------------------------------
__global__ void k_main(
    float* __restrict__ out,
    uint32_t kre0, uint32_t kre1, uint32_t kim0, uint32_t kim1) {

    const int t   = threadIdx.x;
    const int bid = blockIdx.x;
    const int row = bid >> 5;
    const int seg = bid & 31;

    const float rinv = g_rinv[row];   // broadcast load; k_prep wrote this

    const uint32_t j = (uint32_t)(row * 8192 + seg * 256 + t * 2);

    TF4 b = threefry_quad(kre0, kre1, kim0, kim1, j, j + 1);
    float re0 = bits_to_noise(b.ra), re1 = bits_to_noise(b.rb);
    float im0 = bits_to_noise(b.ia), im1 = bits_to_noise(b.ib);
    float2 v;
    v.x = fast_sqrt(fmaf(re0, re0, im0 * im0)) * rinv;
    v.y = fast_sqrt(fmaf(re1, re1, im1 * im1)) * rinv;
    reinterpret_cast<float2*>(out)[j >> 1] = v;

    // d = 0,1 fixup: overwrite with the pre-scaled values from k_prep
    if (seg == 0 && t == 0) {
        reinterpret_cast<float2*>(out)[row * 4096] = g_fix[row];
    }
}

// =========================== host-side replicas ============================
static inline uint32_t h_rotl(uint32_t x, int r) { return (x << r) | (x >> (32 - r)); }
static void h_threefry(uint32_t k0, uint32_t k1, uint32_t x0, uint32_t x1,
                       uint32_t* o0, uint32_t* o1) {
    uint32_t ks2 = 0x1BD11BDAu ^ k0 ^ k1;
#define HTF(r) { x0 += x1; x1 = h_rotl(x1, (r)); x1 ^= x0; }
    x0 += k0;  x1 += k1;
    HTF(13) HTF(15) HTF(26) HTF(6)
    x0 += k1;  x1 += ks2 + 1u;
    HTF(17) HTF(29) HTF(16) HTF(24)
    x0 += ks2; x1 += k0 + 2u;
    HTF(13) HTF(15) HTF(26) HTF(6)
    x0 += k0;  x1 += k1 + 3u;
    HTF(17) HTF(29) HTF(16) HTF(24)
    x0 += k1;  x1 += ks2 + 4u;
    HTF(13) HTF(15) HTF(26) HTF(6)
    x0 += ks2; x1 += k0 + 5u;
#undef HTF
    *o0 = x0; *o1 = x1;
}

static float h_erfinv(float x) {
    float w = -log1pf(-x * x);
    float p;
    if (w < 5.0f) {
        w -= 2.5f;
        p = 2.81022636e-08f;
        p = p * w + 3.43273939e-07f;
        p = p * w + -3.5233877e-06f;
        p = p * w + -4.39150654e-06f;
        p = p * w + 0.00021858087f;
        p = p * w + -0.00125372503f;
        p = p * w + -0.00417768164f;
        p = p * w + 0.246640727f;
        p = p * w + 1.50140941f;
    } else {
        w = sqrtf(w) - 3.0f;
        p = -0.000200214257f;
        p = p * w + 0.000100950558f;
        p = p * w + 0.00134934322f;
        p = p * w + -0.00367342844f;
        p = p * w + 0.00573950773f;
        p = p * w + -0.0076224613f;
        p = p * w + 0.00943887047f;
        p = p * w + 1.00167406f;
        p = p * w + 2.83297682f;
    }
    return p * x;
}

static float h_noise(uint32_t k0, uint32_t k1, uint32_t j) {
    const float LO = -0.99999994039535522461f;
    uint32_t o0, o1;
    h_threefry(k0, k1, 0u, j, &o0, &o1);
    uint32_t bits = o0 ^ o1;
    uint32_t fb = (bits >> 9) | 0x3f800000u;
    float F;
    memcpy(&F, &fb, 4);
    float f = F - 1.0f;
    float u = f * 2.0f + LO;
    if (u < LO) u = LO;
    return h_erfinv(u) * 0.01f;
}

// ---------------------------------------------------------------------------
extern "C" void kernel_launch(void* const* d_in, const int* in_sizes, int n_in,
                              void* d_out, int out_size) {
    // metadata order: x (unused), rx_params, ry_params, rz_params
    const float* rx = (const float*)d_in[1];
    const float* ry = (const float*)d_in[2];
    const float* rz = (const float*)d_in[3];
    float* out = (float*)d_out;

    // foldlike split of key(42) = (0, 42)
    uint32_t kre0, kre1, kim0, kim1;
    h_threefry(0u, 42u, 0u, 0u, &kre0, &kre1);
    h_threefry(0u, 42u, 0u, 1u, &kim0, &kim1);

    // per-row noise-power constants (d = 2..8191): input-independent,
    // deterministically recomputed every call on the host.
    RowConst C;
    for (int row = 0; row < 256; row++) {
        double acc = 0.0;
        uint32_t jbase = (uint32_t)(row * 8192);
        for (int d = 2; d < 8192; d++) {
            float re = h_noise(kre0, kre1, jbase + (uint32_t)d);
            float im = h_noise(kim0, kim1, jbase + (uint32_t)d);
            acc += (double)re * re + (double)im * im;
        }
        C.c[row] = (float)acc;
    }

    k_prep<<<256, 32>>>(rx, ry, rz, kre0, kre1, kim0, kim1, C);
    k_main<<<8192, 128>>>(out, kre0, kre1, kim0, kim1);
}